// round 9
// baseline (speedup 1.0000x reference)
#include <cuda_runtime.h>
#include <cuda_bf16.h>
#include <math.h>

#define BB 512
#define NN 24
#define TT 25
#define IN_F 8
#define LL 64
#define HH 256
#define OUTF 128
#define XIF 72
#define G4 512

typedef unsigned int uint32;

// ---------------- scratch (device globals; allocation-free) ----------------
// fp32 state / GEMM outputs
__device__ float g_c1 [BB*NN*OUTF];
__device__ float g_c2 [BB*NN*OUTF];
__device__ float g_gts[BB*NN*G4];
__device__ float g_p1 [BB*NN*OUTF];
__device__ float g_p2 [BB*NN*OUTF];
__device__ float g_ls [BB*NN*4];
// split activation planes (bf16 hi/lo packed k-pairs)
__device__ uint32 g_xiH[BB*NN*36];  __device__ uint32 g_xiL[BB*NN*36];
__device__ uint32 g_h1H[BB*NN*64];  __device__ uint32 g_h1L[BB*NN*64];
__device__ uint32 g_h2H[BB*NN*64];  __device__ uint32 g_h2L[BB*NN*64];
__device__ uint32 g_yiH[BB*NN*64];  __device__ uint32 g_yiL[BB*NN*64];
__device__ uint32 g_encH[BB*NN*128]; __device__ uint32 g_encL[BB*NN*128];
// split weight planes
__device__ uint32 g_wx0H[24*36*512]; __device__ uint32 g_wx0L[24*36*512];
__device__ uint32 g_wh0H[24*64*512]; __device__ uint32 g_wh0L[24*64*512];
__device__ uint32 g_wx1H[24*64*512]; __device__ uint32 g_wx1L[24*64*512];
__device__ uint32 g_wh1H[24*64*512]; __device__ uint32 g_wh1L[24*64*512];
__device__ uint32 g_fcH [24*64*128]; __device__ uint32 g_fcL [24*64*128];
__device__ uint32 g_fc2H[24*64*128]; __device__ uint32 g_fc2L[24*64*128];
__device__ uint32 g_ih1H[128*128];   __device__ uint32 g_ih1L[128*128];
__device__ uint32 g_ih2H[128*128];   __device__ uint32 g_ih2L[128*128];

__device__ __forceinline__ float sigf(float v) { return 1.0f / (1.0f + expf(-v)); }

// split a pair of floats into packed bf16 hi and lo words
__device__ __forceinline__ void splitpair(float a, float b, uint32& h, uint32& l) {
    __nv_bfloat16 ha = __float2bfloat16_rn(a);
    __nv_bfloat16 hb = __float2bfloat16_rn(b);
    float ra = a - __bfloat162float(ha);
    float rb = b - __bfloat162float(hb);
    __nv_bfloat162 hh; hh.x = ha; hh.y = hb;
    __nv_bfloat162 ll; ll.x = __float2bfloat16_rn(ra); ll.y = __float2bfloat16_rn(rb);
    h = *reinterpret_cast<uint32*>(&hh);
    l = *reinterpret_cast<uint32*>(&ll);
}

__device__ __forceinline__ void mma_bf16(
    float& d0, float& d1, float& d2, float& d3,
    uint32 a0, uint32 a1, uint32 a2, uint32 a3, uint32 b0, uint32 b1)
{
    asm volatile(
        "mma.sync.aligned.m16n8k16.row.col.f32.bf16.bf16.f32 "
        "{%0,%1,%2,%3}, {%4,%5,%6,%7}, {%8,%9}, {%0,%1,%2,%3};"
        : "+f"(d0), "+f"(d1), "+f"(d2), "+f"(d3)
        : "r"(a0), "r"(a1), "r"(a2), "r"(a3), "r"(b0), "r"(b1));
}

// ---------------- generic pre-split kernel ----------------
// word w packs src[2w - (w%O)] and src[2w - (w%O) + O]  (O=1 -> consecutive)
__global__ void ksplit(const float* __restrict__ src, uint32* __restrict__ H,
                       uint32* __restrict__ L, int O, int total)
{
    int w = blockIdx.x * blockDim.x + threadIdx.x;
    if (w >= total) return;
    int o = w % O;
    long off = 2L * w - o;
    splitpair(src[off], src[off + O], H[w], L[w]);
}

// ---------------- bf16x2-split tensor-core GEMM (pre-split operands) ----------
#define KC 16
#define AP 12
#define BP 136
#define ASZ (128 * AP)
#define BSZ (8 * BP)

__device__ __forceinline__ void bf_phase(
    const uint32* __restrict__ AH, const uint32* __restrict__ AL, int ldaw, int K,
    const uint32* __restrict__ BH, const uint32* __restrict__ BL, int ldw,
    int col0, int row0,
    int t, uint32* AsH, uint32* AsL, uint32* BsH, uint32* BsL,
    float (&acc)[4][4][4], int wm, int wn, int g, int tg)
{
    const int nch = (K + KC - 1) / KC;
    const int arow = t >> 1, akp0 = (t & 1) * 4;   // A: 4 k-pair words per thread
    const int bkp = t >> 5, bcol = (t & 31) * 4;   // B: 4 n words per thread
    const uint4 z4 = make_uint4(0u, 0u, 0u, 0u);
    uint4 ahv, alv, bhv, blv;

    const uint32* aH = &AH[(long)(row0 + arow) * ldaw + akp0];
    const uint32* aL = &AL[(long)(row0 + arow) * ldaw + akp0];
    const uint32* bH = &BH[(long)bkp * ldw + col0 + bcol];
    const uint32* bL = &BL[(long)bkp * ldw + col0 + bcol];
    int akp = akp0, bkg = bkp;

    {
        bool va = (akp * 2 < K);
        ahv = va ? *(const uint4*)aH : z4;
        alv = va ? *(const uint4*)aL : z4;
        bool vb = (bkg * 2 < K);
        bhv = vb ? *(const uint4*)bH : z4;
        blv = vb ? *(const uint4*)bL : z4;
    }
    *(uint4*)&AsH[arow * AP + akp0] = ahv;
    *(uint4*)&AsL[arow * AP + akp0] = alv;
    *(uint4*)&BsH[bkp * BP + bcol] = bhv;
    *(uint4*)&BsL[bkp * BP + bcol] = blv;
    __syncthreads();

    for (int c = 0; c < nch; c++) {
        const int buf = c & 1;
        uint32* ah_s = AsH + buf * ASZ;
        uint32* al_s = AsL + buf * ASZ;
        uint32* bh_s = BsH + buf * BSZ;
        uint32* bl_s = BsL + buf * BSZ;

        if (c + 1 < nch) {
            aH += 8; aL += 8; akp += 8;
            bH += (long)8 * ldw; bL += (long)8 * ldw; bkg += 8;
            bool va = (akp * 2 < K);
            ahv = va ? *(const uint4*)aH : z4;
            alv = va ? *(const uint4*)aL : z4;
            bool vb = (bkg * 2 < K);
            bhv = vb ? *(const uint4*)bH : z4;
            blv = vb ? *(const uint4*)bL : z4;
        }

        uint32 ah[4][4], al[4][4];
        #pragma unroll
        for (int i = 0; i < 4; i++) {
            int base = (wm * 64 + i * 16 + g) * AP;
            ah[i][0] = ah_s[base + tg];
            ah[i][1] = ah_s[base + 8 * AP + tg];
            ah[i][2] = ah_s[base + tg + 4];
            ah[i][3] = ah_s[base + 8 * AP + tg + 4];
            al[i][0] = al_s[base + tg];
            al[i][1] = al_s[base + 8 * AP + tg];
            al[i][2] = al_s[base + tg + 4];
            al[i][3] = al_s[base + 8 * AP + tg + 4];
        }
        #pragma unroll
        for (int j = 0; j < 4; j++) {
            int nc = wn * 32 + j * 8 + g;
            uint32 bh0 = bh_s[tg * BP + nc];
            uint32 bh1 = bh_s[(tg + 4) * BP + nc];
            uint32 bl0 = bl_s[tg * BP + nc];
            uint32 bl1 = bl_s[(tg + 4) * BP + nc];
            #pragma unroll
            for (int i = 0; i < 4; i++) {
                mma_bf16(acc[i][j][0], acc[i][j][1], acc[i][j][2], acc[i][j][3],
                         ah[i][0], ah[i][1], ah[i][2], ah[i][3], bh0, bh1);
                mma_bf16(acc[i][j][0], acc[i][j][1], acc[i][j][2], acc[i][j][3],
                         ah[i][0], ah[i][1], ah[i][2], ah[i][3], bl0, bl1);
                mma_bf16(acc[i][j][0], acc[i][j][1], acc[i][j][2], acc[i][j][3],
                         al[i][0], al[i][1], al[i][2], al[i][3], bh0, bh1);
            }
        }

        if (c + 1 < nch) {
            uint32* nah = AsH + (1 - buf) * ASZ;
            uint32* nal = AsL + (1 - buf) * ASZ;
            uint32* nbh = BsH + (1 - buf) * BSZ;
            uint32* nbl = BsL + (1 - buf) * BSZ;
            *(uint4*)&nah[arow * AP + akp0] = ahv;
            *(uint4*)&nal[arow * AP + akp0] = alv;
            *(uint4*)&nbh[bkp * BP + bcol] = bhv;
            *(uint4*)&nbl[bkp * BP + bcol] = blv;
            __syncthreads();
        }
    }
    __syncthreads();
}

// C[node] = A1[node] @ W1[node] (+ A2[node] @ W2[node]) + bias[node]
// blocks with blockIdx.z >= nodes use the "alt" weight/bias/output set.
__global__ __launch_bounds__(256) void gemm_bf(
    const uint32* __restrict__ A1H, const uint32* __restrict__ A1L,
    long a1n, int lda1w, int K1,
    const uint32* __restrict__ A2H, const uint32* __restrict__ A2L,
    long a2n, int lda2w, int K2,
    const uint32* __restrict__ W1H, const uint32* __restrict__ W1L,
    const uint32* __restrict__ W1bH, const uint32* __restrict__ W1bL, long w1n,
    const uint32* __restrict__ W2H, const uint32* __restrict__ W2L, long w2n,
    const float* __restrict__ bias, const float* __restrict__ biasb, long bn,
    float* __restrict__ C, float* __restrict__ Cb, long cn, int ldc, int O, int nodes)
{
    __shared__ uint32 AsH[2 * ASZ];
    __shared__ uint32 AsL[2 * ASZ];
    __shared__ uint32 BsH[2 * BSZ];
    __shared__ uint32 BsL[2 * BSZ];

    int z = blockIdx.z, node = z;
    const uint32* w1h = W1H; const uint32* w1l = W1L;
    const float* bsrc = bias; float* c = C;
    if (z >= nodes) { node = z - nodes; w1h = W1bH; w1l = W1bL; bsrc = biasb; c = Cb; }

    const int t = threadIdx.x;
    const int w = t >> 5, lane = t & 31;
    const int wm = w >> 2, wn = w & 3;
    const int g = lane >> 2, tg = lane & 3;
    const int row0 = blockIdx.y * 128;
    const int col0 = blockIdx.x * 128;

    float acc[4][4][4];
    #pragma unroll
    for (int i = 0; i < 4; i++)
        #pragma unroll
        for (int j = 0; j < 4; j++)
            #pragma unroll
            for (int r = 0; r < 4; r++) acc[i][j][r] = 0.f;

    bf_phase(A1H + (long)node * a1n, A1L + (long)node * a1n, lda1w, K1,
             w1h + (long)node * w1n, w1l + (long)node * w1n, O, col0,
             row0, t, AsH, AsL, BsH, BsL, acc, wm, wn, g, tg);
    if (K2 > 0)
        bf_phase(A2H + (long)node * a2n, A2L + (long)node * a2n, lda2w, K2,
                 W2H + (long)node * w2n, W2L + (long)node * w2n, O, col0,
                 row0, t, AsH, AsL, BsH, BsL, acc, wm, wn, g, tg);

    const float* bp = bsrc + (long)node * bn;
    float* cbase = c + (long)node * cn;
    #pragma unroll
    for (int j = 0; j < 4; j++) {
        int col = col0 + wn * 32 + j * 8 + tg * 2;
        float2 bv = *(const float2*)&bp[col];
        #pragma unroll
        for (int i = 0; i < 4; i++) {
            int r = row0 + wm * 64 + i * 16 + g;
            float2 v0 = make_float2(acc[i][j][0] + bv.x, acc[i][j][1] + bv.y);
            float2 v1 = make_float2(acc[i][j][2] + bv.x, acc[i][j][3] + bv.y);
            *(float2*)&cbase[(long)r * ldc + col] = v0;
            *(float2*)&cbase[(long)(r + 8) * ldc + col] = v1;
        }
    }
}

// ---------------- G-mix + LSTM pointwise (split h / yi output) ----------------
// grid (2, 512): blockIdx.x = oc-half (64 ch = 32 pairs), blockIdx.y = b. 256 thr.
__global__ __launch_bounds__(256) void k_mix_lstm_f(
    const float* __restrict__ gp, const float* __restrict__ G,
    uint32* __restrict__ hH, uint32* __restrict__ hL, float* __restrict__ c,
    uint32* __restrict__ yiH, uint32* __restrict__ yiL)
{
    __shared__ float sg[NN * 256];   // [n][gate*64 + j]
    __shared__ float sG[NN * NN];
    const int och = blockIdx.x, b = blockIdx.y;
    const int t = threadIdx.x;
    const float* src = gp + (long)b * NN * G4;
    for (int e4 = t; e4 < NN * 256 / 4; e4 += 256) {
        int e = e4 * 4;
        int n = e >> 8, col = e & 255, gg = col >> 6, j = col & 63;
        *(float4*)&sg[e] = *(const float4*)&src[n * G4 + gg * 128 + och * 64 + j];
    }
    for (int e = t; e < NN * NN; e += 256) sG[e] = G[e];
    __syncthreads();

    const int ocp = t & 31;           // channel pair within half
    const int m0 = (t >> 5) * 3;      // 3 m per thread
    float acc[3][4][2];
    #pragma unroll
    for (int j = 0; j < 3; j++)
        #pragma unroll
        for (int gg = 0; gg < 4; gg++) { acc[j][gg][0] = 0.f; acc[j][gg][1] = 0.f; }

    for (int n = 0; n < NN; n++) {
        float w0 = sG[(m0 + 0) * NN + n];
        float w1 = sG[(m0 + 1) * NN + n];
        float w2 = sG[(m0 + 2) * NN + n];
        #pragma unroll
        for (int gg = 0; gg < 4; gg++) {
            float v0 = sg[n * 256 + gg * 64 + 2 * ocp];
            float v1 = sg[n * 256 + gg * 64 + 2 * ocp + 1];
            acc[0][gg][0] += w0 * v0; acc[0][gg][1] += w0 * v1;
            acc[1][gg][0] += w1 * v0; acc[1][gg][1] += w1 * v1;
            acc[2][gg][0] += w2 * v0; acc[2][gg][1] += w2 * v1;
        }
    }
    #pragma unroll
    for (int j = 0; j < 3; j++) {
        int m = m0 + j;
        long cidx = ((long)b * NN + m) * OUTF + och * 64 + 2 * ocp;
        float2 cv = *(float2*)&c[cidx];
        float cc0 = sigf(acc[j][1][0]) * cv.x + sigf(acc[j][0][0]) * tanhf(acc[j][2][0]);
        float cc1 = sigf(acc[j][1][1]) * cv.y + sigf(acc[j][0][1]) * tanhf(acc[j][2][1]);
        float hh0 = sigf(acc[j][3][0]) * tanhf(cc0);
        float hh1 = sigf(acc[j][3][1]) * tanhf(cc1);
        *(float2*)&c[cidx] = make_float2(cc0, cc1);
        long widx = ((long)b * NN + m) * 64 + och * 32 + ocp;
        splitpair(hh0, hh1, hH[widx], hL[widx]);
        if (yiH) splitpair(tanhf(hh0), tanhf(hh1), yiH[widx], yiL[widx]);
    }
}

// ---------------- init mix: h0/c0 into both LSTM states (split h) ------------
__global__ __launch_bounds__(256) void k_mix_init_f(
    const float* __restrict__ p1, const float* __restrict__ p2,
    const float* __restrict__ G)
{
    __shared__ float s1[NN * OUTF];
    __shared__ float s2[NN * OUTF];
    __shared__ float sG[NN * NN];
    const int b = blockIdx.x;
    const int t = threadIdx.x;
    const float* q1 = p1 + (long)b * NN * OUTF;
    const float* q2 = p2 + (long)b * NN * OUTF;
    for (int e4 = t; e4 < NN * OUTF / 4; e4 += 256) {
        *(float4*)&s1[e4 * 4] = *(const float4*)&q1[e4 * 4];
        *(float4*)&s2[e4 * 4] = *(const float4*)&q2[e4 * 4];
    }
    for (int e = t; e < NN * NN; e += 256) sG[e] = G[e];
    __syncthreads();

    const int ocp = t & 63;           // 64 channel pairs
    const int m0 = (t >> 6) * 6;      // 6 m per thread
    float a1[6][2], a2[6][2];
    #pragma unroll
    for (int j = 0; j < 6; j++) { a1[j][0] = a1[j][1] = 0.f; a2[j][0] = a2[j][1] = 0.f; }
    for (int n = 0; n < NN; n++) {
        float v10 = s1[n * OUTF + 2 * ocp], v11 = s1[n * OUTF + 2 * ocp + 1];
        float v20 = s2[n * OUTF + 2 * ocp], v21 = s2[n * OUTF + 2 * ocp + 1];
        #pragma unroll
        for (int j = 0; j < 6; j++) {
            float w = sG[(m0 + j) * NN + n];
            a1[j][0] += w * v10; a1[j][1] += w * v11;
            a2[j][0] += w * v20; a2[j][1] += w * v21;
        }
    }
    #pragma unroll
    for (int j = 0; j < 6; j++) {
        int m = m0 + j;
        long widx = ((long)b * NN + m) * 64 + ocp;
        uint32 h, l;
        splitpair(a1[j][0], a1[j][1], h, l);
        g_h1H[widx] = h; g_h1L[widx] = l;
        g_h2H[widx] = h; g_h2L[widx] = l;
        long cidx = ((long)b * NN + m) * OUTF + 2 * ocp;
        *(float2*)&g_c1[cidx] = make_float2(a2[j][0], a2[j][1]);
        *(float2*)&g_c2[cidx] = make_float2(a2[j][0], a2[j][1]);
    }
}

// ---------------- init xi (split) / loc_start ----------------
__global__ void k_init_xi(const float* __restrict__ x, const float* __restrict__ z)
{
    int w = blockIdx.x * blockDim.x + threadIdx.x;
    if (w >= BB * NN * 36) return;
    int bn = w / 36, j = w % 36;
    int k0 = 2 * j;
    float v0, v1;
    if (k0 < LL) {
        v0 = z[(long)bn * LL + k0];
        v1 = z[(long)bn * LL + k0 + 1];
    } else {
        v0 = x[(long)bn * IN_F + (k0 - LL)];
        v1 = x[(long)bn * IN_F + (k0 - LL) + 1];
        if (j == 32) { g_ls[(long)bn * 4 + 0] = v0; g_ls[(long)bn * 4 + 1] = v1; }
        if (j == 33) { g_ls[(long)bn * 4 + 2] = v0; g_ls[(long)bn * 4 + 3] = v1; }
    }
    splitpair(v0, v1, g_xiH[w], g_xiL[w]);
}

// ---------------- fused tail: mix+tanh, head projections, final --------------
__global__ __launch_bounds__(256) void k_tail(
    const float* __restrict__ p1, const float* __restrict__ p2,
    const float* __restrict__ G,
    const float* __restrict__ locW, const float* __restrict__ locb,
    const float* __restrict__ logzW, const float* __restrict__ logzb,
    float* __restrict__ out, int t)
{
    __shared__ float s1[NN * OUTF];
    __shared__ float s2[NN * OUTF];
    __shared__ float sG[NN * NN];
    __shared__ float hp[NN][8];
    const int b = blockIdx.x;
    const int tid = threadIdx.x;
    const float* q1 = p1 + (long)b * NN * OUTF;
    const float* q2 = p2 + (long)b * NN * OUTF;
    for (int e4 = tid; e4 < NN * OUTF / 4; e4 += 256) {
        *(float4*)&s1[e4 * 4] = *(const float4*)&q1[e4 * 4];
        *(float4*)&s2[e4 * 4] = *(const float4*)&q2[e4 * 4];
    }
    for (int e = tid; e < NN * NN; e += 256) sG[e] = G[e];
    __syncthreads();

    // --- stage 1: G-mix + tanh into registers ---
    const int ocl = tid & 127;
    const int m0 = (tid >> 7) * 12;
    float r1[12], r2[12];
    #pragma unroll
    for (int mg = 0; mg < 3; mg++) {
        float a1[4] = {0.f, 0.f, 0.f, 0.f};
        float a2[4] = {0.f, 0.f, 0.f, 0.f};
        int mb = m0 + mg * 4;
        for (int n = 0; n < NN; n++) {
            float v1 = s1[n * OUTF + ocl];
            float v2 = s2[n * OUTF + ocl];
            #pragma unroll
            for (int j = 0; j < 4; j++) {
                float w = sG[(mb + j) * NN + n];
                a1[j] += w * v1; a2[j] += w * v2;
            }
        }
        #pragma unroll
        for (int j = 0; j < 4; j++) {
            r1[mg * 4 + j] = tanhf(a1[j]);
            r2[mg * 4 + j] = tanhf(a2[j]);
        }
    }
    __syncthreads();
    #pragma unroll
    for (int k = 0; k < 12; k++) {
        s1[(m0 + k) * OUTF + ocl] = r1[k];
        s2[(m0 + k) * OUTF + ocl] = r2[k];
    }
    __syncthreads();

    // --- stage 2: head projections (warp w handles m = w*3..w*3+2) ---
    const int wid = tid >> 5, lane = tid & 31;
    #pragma unroll
    for (int mm = 0; mm < 3; mm++) {
        int m = wid * 3 + mm;
        float4 v1 = *(const float4*)&s1[m * OUTF + lane * 4];
        float4 v2 = *(const float4*)&s2[m * OUTF + lane * 4];
        float a[7] = {0.f, 0.f, 0.f, 0.f, 0.f, 0.f, 0.f};
        float x1[4] = {v1.x, v1.y, v1.z, v1.w};
        float x2[4] = {v2.x, v2.y, v2.z, v2.w};
        #pragma unroll
        for (int j = 0; j < 4; j++) {
            int f = lane * 4 + j;
            a[0] += x1[j] * locW[f * 3 + 0];
            a[1] += x1[j] * locW[f * 3 + 1];
            a[2] += x1[j] * locW[f * 3 + 2];
            a[3] += x2[j] * logzW[f * 4 + 0];
            a[4] += x2[j] * logzW[f * 4 + 1];
            a[5] += x2[j] * logzW[f * 4 + 2];
            a[6] += x2[j] * logzW[f * 4 + 3];
        }
        #pragma unroll
        for (int s = 16; s > 0; s >>= 1)
            #pragma unroll
            for (int k = 0; k < 7; k++)
                a[k] += __shfl_xor_sync(0xFFFFFFFFu, a[k], s);
        if (lane == 0) {
            #pragma unroll
            for (int k = 0; k < 7; k++) hp[m][k] = a[k];
        }
    }
    __syncthreads();

    // --- stage 3: final (G-mix of heads, normalize, quat, outputs) ---
    if (tid < NN) {
        const int m = tid;
        float l0 = locb[0], l1 = locb[1], l2 = locb[2];
        float z0 = logzb[0], z1 = logzb[1], z2 = logzb[2], z3 = logzb[3];
        #pragma unroll 4
        for (int n = 0; n < NN; n++) {
            float w = sG[m * NN + n];
            l0 += w * hp[n][0]; l1 += w * hp[n][1]; l2 += w * hp[n][2];
            z0 += w * hp[n][3]; z1 += w * hp[n][4];
            z2 += w * hp[n][5]; z3 += w * hp[n][6];
        }
        float r = rsqrtf(1.0f + l0 * l0 + l1 * l1 + l2 * l2);
        float d0 = r, d1 = l0 * r, d2 = l1 * r, d3 = l2 * r;
        float* ls = &g_ls[((long)b * NN + m) * 4];
        float w1 = ls[0], x1 = ls[1], y1 = ls[2], zz1 = ls[3];
        float q0 = w1 * d0 - x1 * d1 - y1 * d2 - zz1 * d3;
        float q1v = w1 * d1 + x1 * d0 + y1 * d3 - zz1 * d2;
        float q2v = w1 * d2 - x1 * d3 + y1 * d0 + zz1 * d1;
        float q3v = w1 * d3 + x1 * d2 - y1 * d1 + zz1 * d0;
        ls[0] = q0; ls[1] = q1v; ls[2] = q2v; ls[3] = q3v;
        long ob = (((long)b * TT + t) * NN + m) * 4;
        out[ob + 0] = q0; out[ob + 1] = q1v; out[ob + 2] = q2v; out[ob + 3] = q3v;
        const long ZOFF = (long)BB * TT * NN * 4;
        out[ZOFF + ob + 0] = z0; out[ZOFF + ob + 1] = z1;
        out[ZOFF + ob + 2] = z2; out[ZOFF + ob + 3] = z3;
        long wbase = ((long)b * NN + m) * 36;
        splitpair(q0,  q1v, g_xiH[wbase + 32], g_xiL[wbase + 32]);
        splitpair(q2v, q3v, g_xiH[wbase + 33], g_xiL[wbase + 33]);
        splitpair(d0,  d1,  g_xiH[wbase + 34], g_xiL[wbase + 34]);
        splitpair(d2,  d3,  g_xiH[wbase + 35], g_xiL[wbase + 35]);
    }
}

// ---------------- host ----------------
static inline void* sym(const void* s) { void* p; cudaGetSymbolAddress(&p, s); return p; }

extern "C" void kernel_launch(void* const* d_in, const int* in_sizes, int n_in,
                              void* d_out, int out_size)
{
    const float* x     = (const float*)d_in[0];
    const float* enc   = (const float*)d_in[1];
    const float* z     = (const float*)d_in[2];
    /* d_in[3] = y, unused */
    const float* G     = (const float*)d_in[4];
    const float* Wx0   = (const float*)d_in[5];
    const float* Wh0   = (const float*)d_in[6];
    const float* b0    = (const float*)d_in[7];
    const float* Wx1   = (const float*)d_in[8];
    const float* Wh1   = (const float*)d_in[9];
    const float* b1    = (const float*)d_in[10];
    const float* fcW   = (const float*)d_in[11];
    const float* fcb   = (const float*)d_in[12];
    const float* fc2W  = (const float*)d_in[13];
    const float* fc2b  = (const float*)d_in[14];
    const float* ih1W  = (const float*)d_in[15];
    const float* ih1b  = (const float*)d_in[16];
    const float* ih2W  = (const float*)d_in[17];
    const float* ih2b  = (const float*)d_in[18];
    const float* locW  = (const float*)d_in[19];
    const float* locb  = (const float*)d_in[20];
    const float* logzW = (const float*)d_in[21];
    const float* logzb = (const float*)d_in[22];
    float* out = (float*)d_out;

    float*  c1  = (float*) sym(g_c1);
    float*  c2  = (float*) sym(g_c2);
    float*  gts = (float*) sym(g_gts);
    float*  p1  = (float*) sym(g_p1);
    float*  p2  = (float*) sym(g_p2);
    uint32 *xiH = (uint32*)sym(g_xiH), *xiL = (uint32*)sym(g_xiL);
    uint32 *h1H = (uint32*)sym(g_h1H), *h1L = (uint32*)sym(g_h1L);
    uint32 *h2H = (uint32*)sym(g_h2H), *h2L = (uint32*)sym(g_h2L);
    uint32 *yiH = (uint32*)sym(g_yiH), *yiL = (uint32*)sym(g_yiL);
    uint32 *encH= (uint32*)sym(g_encH),*encL= (uint32*)sym(g_encL);
    uint32 *wx0H=(uint32*)sym(g_wx0H), *wx0L=(uint32*)sym(g_wx0L);
    uint32 *wh0H=(uint32*)sym(g_wh0H), *wh0L=(uint32*)sym(g_wh0L);
    uint32 *wx1H=(uint32*)sym(g_wx1H), *wx1L=(uint32*)sym(g_wx1L);
    uint32 *wh1H=(uint32*)sym(g_wh1H), *wh1L=(uint32*)sym(g_wh1L);
    uint32 *fcH =(uint32*)sym(g_fcH),  *fcL =(uint32*)sym(g_fcL);
    uint32 *fc2H=(uint32*)sym(g_fc2H), *fc2L=(uint32*)sym(g_fc2L);
    uint32 *ih1H=(uint32*)sym(g_ih1H), *ih1L=(uint32*)sym(g_ih1L);
    uint32 *ih2H=(uint32*)sym(g_ih2H), *ih2L=(uint32*)sym(g_ih2L);

    // ---- one-time splits ----
    auto SPLIT = [](const float* s, uint32* H, uint32* L, int O, int total) {
        ksplit<<<(total + 255) / 256, 256>>>(s, H, L, O, total);
    };
    SPLIT(enc,  encH, encL, 1,   BB * NN * 128);
    SPLIT(Wx0,  wx0H, wx0L, 512, 24 * 36 * 512);
    SPLIT(Wh0,  wh0H, wh0L, 512, 24 * 64 * 512);
    SPLIT(Wx1,  wx1H, wx1L, 512, 24 * 64 * 512);
    SPLIT(Wh1,  wh1H, wh1L, 512, 24 * 64 * 512);
    SPLIT(fcW,  fcH,  fcL,  128, 24 * 64 * 128);
    SPLIT(fc2W, fc2H, fc2L, 128, 24 * 64 * 128);
    SPLIT(ih1W, ih1H, ih1L, 128, 128 * 128);
    SPLIT(ih2W, ih2H, ih2L, 128, 128 * 128);
    k_init_xi<<<(BB * NN * 36 + 255) / 256, 256>>>(x, z);

    // init: enc @ ih1 -> p1 (z=0), enc @ ih2 -> p2 (z=1)
    {
        dim3 grid(1, (BB * NN) / 128, 2);
        gemm_bf<<<grid, 256>>>(encH, encL, 0, 128, 256,
                               encH, encL, 0, 128, 0,
                               ih1H, ih1L, ih2H, ih2L, 0,
                               ih1H, ih1L, 0,
                               ih1b, ih2b, 0,
                               p1, p2, 0, OUTF, OUTF, 1);
    }
    k_mix_init_f<<<BB, 256>>>(p1, p2, G);

    // ---- T sequential steps ----
    for (int t = 0; t < TT; t++) {
        {   // LSTM1 gates: xi @ Wx0[n] + h1 @ Wh0[n] + b0[n]
            dim3 grid(G4 / 128, BB / 128, NN);
            gemm_bf<<<grid, 256>>>(xiH, xiL, 36, NN * 36, XIF,
                                   h1H, h1L, 64, NN * 64, OUTF,
                                   wx0H, wx0L, wx0H, wx0L, 36 * 512,
                                   wh0H, wh0L, 64 * 512,
                                   b0, b0, G4,
                                   gts, gts, G4, NN * G4, G4, NN);
        }
        { dim3 grid(2, BB); k_mix_lstm_f<<<grid, 256>>>(gts, G, h1H, h1L, c1, nullptr, nullptr); }
        {   // LSTM2 gates: h1 @ Wx1[n] + h2 @ Wh1[n] + b1[n]
            dim3 grid(G4 / 128, BB / 128, NN);
            gemm_bf<<<grid, 256>>>(h1H, h1L, 64, NN * 64, OUTF,
                                   h2H, h2L, 64, NN * 64, OUTF,
                                   wx1H, wx1L, wx1H, wx1L, 64 * 512,
                                   wh1H, wh1L, 64 * 512,
                                   b1, b1, G4,
                                   gts, gts, G4, NN * G4, G4, NN);
        }
        { dim3 grid(2, BB); k_mix_lstm_f<<<grid, 256>>>(gts, G, h2H, h2L, c2, yiH, yiL); }
        {   // fused fc / fc2: yi @ fc_W[n] -> p1 (z<24), yi @ fc2_W[n] -> p2
            dim3 grid(1, BB / 128, 2 * NN);
            gemm_bf<<<grid, 256>>>(yiH, yiL, 64, NN * 64, OUTF,
                                   yiH, yiL, 64, NN * 64, 0,
                                   fcH, fcL, fc2H, fc2L, 64 * 128,
                                   fcH, fcL, 0,
                                   fcb, fc2b, OUTF,
                                   p1, p2, OUTF, NN * OUTF, OUTF, NN);
        }
        k_tail<<<BB, 256>>>(p1, p2, G, locW, locb, logzW, logzb, out, t);
    }
}

// round 10
// speedup vs baseline: 1.1360x; 1.1360x over previous
#include <cuda_runtime.h>
#include <cuda_bf16.h>
#include <math.h>

#define BB 512
#define NN 24
#define TT 25
#define IN_F 8
#define LL 64
#define HH 256
#define OUTF 128
#define XIF 72
#define G4 512

typedef unsigned int uint32;

// ---------------- scratch (device globals; allocation-free) ----------------
__device__ float g_xi [BB*NN*XIF];
__device__ float g_h1 [BB*NN*OUTF];
__device__ float g_c1 [BB*NN*OUTF];
__device__ float g_h2 [BB*NN*OUTF];
__device__ float g_c2 [BB*NN*OUTF];
__device__ float g_gts[BB*NN*G4];
__device__ float g_p1 [BB*NN*OUTF];
__device__ float g_p2 [BB*NN*OUTF];
__device__ float g_yi [BB*NN*OUTF];
__device__ float g_ls [BB*NN*4];

__device__ __forceinline__ float sigf(float v) { return 1.0f / (1.0f + expf(-v)); }

// split a pair of floats (consecutive k) into packed bf16 hi and lo words
__device__ __forceinline__ void splitpair(float a, float b, uint32& h, uint32& l) {
    __nv_bfloat16 ha = __float2bfloat16_rn(a);
    __nv_bfloat16 hb = __float2bfloat16_rn(b);
    float ra = a - __bfloat162float(ha);
    float rb = b - __bfloat162float(hb);
    __nv_bfloat162 hh; hh.x = ha; hh.y = hb;
    __nv_bfloat162 ll; ll.x = __float2bfloat16_rn(ra); ll.y = __float2bfloat16_rn(rb);
    h = *reinterpret_cast<uint32*>(&hh);
    l = *reinterpret_cast<uint32*>(&ll);
}

__device__ __forceinline__ void mma_bf16(
    float& d0, float& d1, float& d2, float& d3,
    uint32 a0, uint32 a1, uint32 a2, uint32 a3, uint32 b0, uint32 b1)
{
    asm volatile(
        "mma.sync.aligned.m16n8k16.row.col.f32.bf16.bf16.f32 "
        "{%0,%1,%2,%3}, {%4,%5,%6,%7}, {%8,%9}, {%0,%1,%2,%3};"
        : "+f"(d0), "+f"(d1), "+f"(d2), "+f"(d3)
        : "r"(a0), "r"(a1), "r"(a2), "r"(a3), "r"(b0), "r"(b1));
}

__device__ __forceinline__ void ldsm_x4(
    uint32& r0, uint32& r1, uint32& r2, uint32& r3, const uint32* p)
{
    uint32 addr = (uint32)__cvta_generic_to_shared(p);
    asm volatile(
        "ldmatrix.sync.aligned.m8n8.x4.shared.b16 {%0,%1,%2,%3}, [%4];"
        : "=r"(r0), "=r"(r1), "=r"(r2), "=r"(r3) : "r"(addr));
}

// ---------------- bf16x2-split tensor-core GEMM ----------------
// 128x128 block, 8 warps (2x4), 64x32 warp tile, K-chunk 16, double-buffered.
// A words: [row][kp] pitch AP (kp = k/2, 8 used). B words: [kp][n] pitch BP.
#define KC 16
#define AP 12
#define BP 136
#define ASZ (128 * AP)
#define BSZ (8 * BP)

__device__ __forceinline__ void bf_phase(
    const float* __restrict__ A, int lda, int K,
    const float* __restrict__ W, int ldw, int col0, int row0,
    int t, uint32* AsH, uint32* AsL, uint32* BsH, uint32* BsL,
    float (&acc)[4][4][4], int wm, int wn, int g, int tg)
{
    const int nch = (K + KC - 1) / KC;
    const int arow = t >> 1, akp0 = (t & 1) * 4;
    const int bkp = t >> 5, bn = (t & 31) * 4;
    const float4 z4 = make_float4(0.f, 0.f, 0.f, 0.f);
    float4 a0, a1, b0, b1;

    // ldmatrix lane geometry for A fragments
    const int lane = t & 31;
    const int afr = ((lane >> 3) & 1) * 8 + (lane & 7);   // fragment row within 16
    const int afc = (lane >> 4) * 4;                      // fragment word column

    const float* aptr = &A[(long)(row0 + arow) * lda + akp0 * 2];
    const float* bptr = &W[(long)(2 * bkp) * ldw + col0 + bn];
    int ka = akp0 * 2;
    int kb = 2 * bkp;

    {
        bool va = (ka < K);
        a0 = va ? *(const float4*)aptr : z4;
        a1 = va ? *(const float4*)(aptr + 4) : z4;
        bool vb = (kb < K);
        b0 = vb ? *(const float4*)bptr : z4;
        b1 = vb ? *(const float4*)(bptr + ldw) : z4;
    }
    {
        uint4 h, l;
        splitpair(a0.x, a0.y, h.x, l.x); splitpair(a0.z, a0.w, h.y, l.y);
        splitpair(a1.x, a1.y, h.z, l.z); splitpair(a1.z, a1.w, h.w, l.w);
        *(uint4*)&AsH[arow * AP + akp0] = h;
        *(uint4*)&AsL[arow * AP + akp0] = l;
        splitpair(b0.x, b1.x, h.x, l.x); splitpair(b0.y, b1.y, h.y, l.y);
        splitpair(b0.z, b1.z, h.z, l.z); splitpair(b0.w, b1.w, h.w, l.w);
        *(uint4*)&BsH[bkp * BP + bn] = h;
        *(uint4*)&BsL[bkp * BP + bn] = l;
    }
    __syncthreads();

    for (int c = 0; c < nch; c++) {
        const int buf = c & 1;
        uint32* ah_s = AsH + buf * ASZ;
        uint32* al_s = AsL + buf * ASZ;
        uint32* bh_s = BsH + buf * BSZ;
        uint32* bl_s = BsL + buf * BSZ;

        if (c + 1 < nch) {
            aptr += KC;
            bptr += (long)KC * ldw;
            ka += KC;
            kb += KC;
            bool va = (ka < K);
            a0 = va ? *(const float4*)aptr : z4;
            a1 = va ? *(const float4*)(aptr + 4) : z4;
            bool vb = (kb < K);
            b0 = vb ? *(const float4*)bptr : z4;
            b1 = vb ? *(const float4*)(bptr + ldw) : z4;
        }

        // A fragments via ldmatrix.x4 (bit-identical to the scalar mapping)
        uint32 ah[4][4], al[4][4];
        #pragma unroll
        for (int i = 0; i < 4; i++) {
            int m0b = wm * 64 + i * 16;
            ldsm_x4(ah[i][0], ah[i][1], ah[i][2], ah[i][3],
                    &ah_s[(m0b + afr) * AP + afc]);
            ldsm_x4(al[i][0], al[i][1], al[i][2], al[i][3],
                    &al_s[(m0b + afr) * AP + afc]);
        }
        #pragma unroll
        for (int j = 0; j < 4; j++) {
            int nc = wn * 32 + j * 8 + g;
            uint32 bh0 = bh_s[tg * BP + nc];
            uint32 bh1 = bh_s[(tg + 4) * BP + nc];
            uint32 bl0 = bl_s[tg * BP + nc];
            uint32 bl1 = bl_s[(tg + 4) * BP + nc];
            #pragma unroll
            for (int i = 0; i < 4; i++) {
                mma_bf16(acc[i][j][0], acc[i][j][1], acc[i][j][2], acc[i][j][3],
                         ah[i][0], ah[i][1], ah[i][2], ah[i][3], bh0, bh1);
                mma_bf16(acc[i][j][0], acc[i][j][1], acc[i][j][2], acc[i][j][3],
                         ah[i][0], ah[i][1], ah[i][2], ah[i][3], bl0, bl1);
                mma_bf16(acc[i][j][0], acc[i][j][1], acc[i][j][2], acc[i][j][3],
                         al[i][0], al[i][1], al[i][2], al[i][3], bh0, bh1);
            }
        }

        if (c + 1 < nch) {
            uint32* nah = AsH + (1 - buf) * ASZ;
            uint32* nal = AsL + (1 - buf) * ASZ;
            uint32* nbh = BsH + (1 - buf) * BSZ;
            uint32* nbl = BsL + (1 - buf) * BSZ;
            uint4 h, l;
            splitpair(a0.x, a0.y, h.x, l.x); splitpair(a0.z, a0.w, h.y, l.y);
            splitpair(a1.x, a1.y, h.z, l.z); splitpair(a1.z, a1.w, h.w, l.w);
            *(uint4*)&nah[arow * AP + akp0] = h;
            *(uint4*)&nal[arow * AP + akp0] = l;
            splitpair(b0.x, b1.x, h.x, l.x); splitpair(b0.y, b1.y, h.y, l.y);
            splitpair(b0.z, b1.z, h.z, l.z); splitpair(b0.w, b1.w, h.w, l.w);
            *(uint4*)&nbh[bkp * BP + bn] = h;
            *(uint4*)&nbl[bkp * BP + bn] = l;
            __syncthreads();
        }
    }
    __syncthreads();
}

// C[node] = A1[node] @ W1[node] (+ A2[node] @ W2[node]) + bias[node]
__global__ __launch_bounds__(256) void gemm_bf(
    const float* __restrict__ A1, long a1n, int lda1, int K1,
    const float* __restrict__ A2, long a2n, int lda2, int K2,
    const float* __restrict__ W1, const float* __restrict__ W1b, long w1n,
    const float* __restrict__ W2, long w2n,
    const float* __restrict__ bias, const float* __restrict__ biasb, long bn,
    float* __restrict__ C, float* __restrict__ Cb, long cn, int ldc, int O, int nodes)
{
    __shared__ uint32 AsH[2 * ASZ];
    __shared__ uint32 AsL[2 * ASZ];
    __shared__ uint32 BsH[2 * BSZ];
    __shared__ uint32 BsL[2 * BSZ];

    int z = blockIdx.z, node = z;
    const float* w1 = W1; const float* bsrc = bias; float* c = C;
    if (z >= nodes) { node = z - nodes; w1 = W1b; bsrc = biasb; c = Cb; }

    const int t = threadIdx.x;
    const int w = t >> 5, lane = t & 31;
    const int wm = w >> 2, wn = w & 3;
    const int g = lane >> 2, tg = lane & 3;
    const int row0 = blockIdx.y * 128;
    const int col0 = blockIdx.x * 128;

    float acc[4][4][4];
    #pragma unroll
    for (int i = 0; i < 4; i++)
        #pragma unroll
        for (int j = 0; j < 4; j++)
            #pragma unroll
            for (int r = 0; r < 4; r++) acc[i][j][r] = 0.f;

    bf_phase(A1 + (long)node * a1n, lda1, K1, w1 + (long)node * w1n, O, col0,
             row0, t, AsH, AsL, BsH, BsL, acc, wm, wn, g, tg);
    if (K2 > 0)
        bf_phase(A2 + (long)node * a2n, lda2, K2, W2 + (long)node * w2n, O, col0,
                 row0, t, AsH, AsL, BsH, BsL, acc, wm, wn, g, tg);

    const float* bp = bsrc + (long)node * bn;
    float* cbase = c + (long)node * cn;
    #pragma unroll
    for (int j = 0; j < 4; j++) {
        int col = col0 + wn * 32 + j * 8 + tg * 2;
        float2 bv = *(const float2*)&bp[col];
        #pragma unroll
        for (int i = 0; i < 4; i++) {
            int r = row0 + wm * 64 + i * 16 + g;
            float2 v0 = make_float2(acc[i][j][0] + bv.x, acc[i][j][1] + bv.y);
            float2 v1 = make_float2(acc[i][j][2] + bv.x, acc[i][j][3] + bv.y);
            *(float2*)&cbase[(long)r * ldc + col] = v0;
            *(float2*)&cbase[(long)(r + 8) * ldc + col] = v1;
        }
    }
}

// ---------------- fast G-mix + LSTM pointwise ----------------
// grid (2, 512): blockIdx.x = oc-half (64 ch), blockIdx.y = b. 256 threads.
__global__ __launch_bounds__(256) void k_mix_lstm_f(
    const float* __restrict__ gp, const float* __restrict__ G,
    float* __restrict__ h, float* __restrict__ c, float* __restrict__ yi)
{
    __shared__ float sg[NN * 256];   // [n][gate*64 + ocl]
    __shared__ float sG[NN * NN];
    const int och = blockIdx.x, b = blockIdx.y;
    const int t = threadIdx.x;
    const float* src = gp + (long)b * NN * G4;
    for (int e4 = t; e4 < NN * 256 / 4; e4 += 256) {
        int e = e4 * 4;
        int n = e >> 8, col = e & 255, g = col >> 6, j = col & 63;
        *(float4*)&sg[e] = *(const float4*)&src[n * G4 + g * 128 + och * 64 + j];
    }
    for (int e = t; e < NN * NN; e += 256) sG[e] = G[e];
    __syncthreads();

    const int ocl = t & 63;
    const int m0 = (t >> 6) * 6;
    float acc[6][4];
    #pragma unroll
    for (int j = 0; j < 6; j++)
        #pragma unroll
        for (int g = 0; g < 4; g++) acc[j][g] = 0.f;
    for (int n = 0; n < NN; n++) {
        float gv0 = sg[n * 256 + ocl];
        float gv1 = sg[n * 256 + 64 + ocl];
        float gv2 = sg[n * 256 + 128 + ocl];
        float gv3 = sg[n * 256 + 192 + ocl];
        #pragma unroll
        for (int j = 0; j < 6; j++) {
            float w = sG[(m0 + j) * NN + n];
            acc[j][0] += w * gv0; acc[j][1] += w * gv1;
            acc[j][2] += w * gv2; acc[j][3] += w * gv3;
        }
    }
    const int oc = och * 64 + ocl;
    #pragma unroll
    for (int j = 0; j < 6; j++) {
        long idx = ((long)b * NN + m0 + j) * OUTF + oc;
        float cc = sigf(acc[j][1]) * c[idx] + sigf(acc[j][0]) * tanhf(acc[j][2]);
        float hh = sigf(acc[j][3]) * tanhf(cc);
        c[idx] = cc;
        h[idx] = hh;
        if (yi) yi[idx] = tanhf(hh);
    }
}

// ---------------- fast init mix: h0/c0 into both LSTM states ----------------
__global__ __launch_bounds__(256) void k_mix_init_f(
    const float* __restrict__ p1, const float* __restrict__ p2,
    const float* __restrict__ G)
{
    __shared__ float s1[NN * OUTF];
    __shared__ float s2[NN * OUTF];
    __shared__ float sG[NN * NN];
    const int b = blockIdx.x;
    const int t = threadIdx.x;
    const float* q1 = p1 + (long)b * NN * OUTF;
    const float* q2 = p2 + (long)b * NN * OUTF;
    for (int e4 = t; e4 < NN * OUTF / 4; e4 += 256) {
        *(float4*)&s1[e4 * 4] = *(const float4*)&q1[e4 * 4];
        *(float4*)&s2[e4 * 4] = *(const float4*)&q2[e4 * 4];
    }
    for (int e = t; e < NN * NN; e += 256) sG[e] = G[e];
    __syncthreads();

    const int ocl = t & 127;
    const int m0 = (t >> 7) * 12;
    #pragma unroll
    for (int mg = 0; mg < 3; mg++) {
        float a1[4] = {0.f, 0.f, 0.f, 0.f};
        float a2[4] = {0.f, 0.f, 0.f, 0.f};
        int mb = m0 + mg * 4;
        for (int n = 0; n < NN; n++) {
            float v1 = s1[n * OUTF + ocl];
            float v2 = s2[n * OUTF + ocl];
            #pragma unroll
            for (int j = 0; j < 4; j++) {
                float w = sG[(mb + j) * NN + n];
                a1[j] += w * v1; a2[j] += w * v2;
            }
        }
        #pragma unroll
        for (int j = 0; j < 4; j++) {
            long idx = ((long)b * NN + mb + j) * OUTF + ocl;
            g_h1[idx] = a1[j]; g_h2[idx] = a1[j];
            g_c1[idx] = a2[j]; g_c2[idx] = a2[j];
        }
    }
}

// ---------------- init xi / loc_start ----------------
__global__ void k_init_xi(const float* __restrict__ x, const float* __restrict__ z)
{
    int idx = blockIdx.x * blockDim.x + threadIdx.x;
    if (idx >= BB * NN * XIF) return;
    int j = idx % XIF;
    int bn = idx / XIF;
    float v;
    if (j < LL) {
        v = z[(long)bn * LL + j];
    } else {
        v = x[(long)bn * IN_F + (j - LL)];
        if (j < LL + 4) g_ls[(long)bn * 4 + (j - LL)] = v;
    }
    g_xi[idx] = v;
}

// ---------------- fused tail: mix+tanh, head projections, final ----------------
// one block per b, 256 threads.
__global__ __launch_bounds__(256) void k_tail(
    const float* __restrict__ p1, const float* __restrict__ p2,
    const float* __restrict__ G,
    const float* __restrict__ locW, const float* __restrict__ locb,
    const float* __restrict__ logzW, const float* __restrict__ logzb,
    float* __restrict__ out, int t)
{
    __shared__ float s1[NN * OUTF];
    __shared__ float s2[NN * OUTF];
    __shared__ float sG[NN * NN];
    __shared__ float hp[NN][8];
    const int b = blockIdx.x;
    const int tid = threadIdx.x;
    const float* q1 = p1 + (long)b * NN * OUTF;
    const float* q2 = p2 + (long)b * NN * OUTF;
    for (int e4 = tid; e4 < NN * OUTF / 4; e4 += 256) {
        *(float4*)&s1[e4 * 4] = *(const float4*)&q1[e4 * 4];
        *(float4*)&s2[e4 * 4] = *(const float4*)&q2[e4 * 4];
    }
    for (int e = tid; e < NN * NN; e += 256) sG[e] = G[e];
    __syncthreads();

    // --- stage 1: G-mix + tanh into registers ---
    const int ocl = tid & 127;
    const int m0 = (tid >> 7) * 12;
    float r1[12], r2[12];
    #pragma unroll
    for (int mg = 0; mg < 3; mg++) {
        float a1[4] = {0.f, 0.f, 0.f, 0.f};
        float a2[4] = {0.f, 0.f, 0.f, 0.f};
        int mb = m0 + mg * 4;
        for (int n = 0; n < NN; n++) {
            float v1 = s1[n * OUTF + ocl];
            float v2 = s2[n * OUTF + ocl];
            #pragma unroll
            for (int j = 0; j < 4; j++) {
                float w = sG[(mb + j) * NN + n];
                a1[j] += w * v1; a2[j] += w * v2;
            }
        }
        #pragma unroll
        for (int j = 0; j < 4; j++) {
            r1[mg * 4 + j] = tanhf(a1[j]);
            r2[mg * 4 + j] = tanhf(a2[j]);
        }
    }
    __syncthreads();
    // overwrite s1/s2 with yi1/yi2
    #pragma unroll
    for (int k = 0; k < 12; k++) {
        s1[(m0 + k) * OUTF + ocl] = r1[k];
        s2[(m0 + k) * OUTF + ocl] = r2[k];
    }
    __syncthreads();

    // --- stage 2: head projections (warp w handles m = w*3..w*3+2) ---
    const int wid = tid >> 5, lane = tid & 31;
    #pragma unroll
    for (int mm = 0; mm < 3; mm++) {
        int m = wid * 3 + mm;
        float4 v1 = *(const float4*)&s1[m * OUTF + lane * 4];
        float4 v2 = *(const float4*)&s2[m * OUTF + lane * 4];
        float a[7] = {0.f, 0.f, 0.f, 0.f, 0.f, 0.f, 0.f};
        float x1[4] = {v1.x, v1.y, v1.z, v1.w};
        float x2[4] = {v2.x, v2.y, v2.z, v2.w};
        #pragma unroll
        for (int j = 0; j < 4; j++) {
            int f = lane * 4 + j;
            a[0] += x1[j] * locW[f * 3 + 0];
            a[1] += x1[j] * locW[f * 3 + 1];
            a[2] += x1[j] * locW[f * 3 + 2];
            a[3] += x2[j] * logzW[f * 4 + 0];
            a[4] += x2[j] * logzW[f * 4 + 1];
            a[5] += x2[j] * logzW[f * 4 + 2];
            a[6] += x2[j] * logzW[f * 4 + 3];
        }
        #pragma unroll
        for (int s = 16; s > 0; s >>= 1)
            #pragma unroll
            for (int k = 0; k < 7; k++)
                a[k] += __shfl_xor_sync(0xFFFFFFFFu, a[k], s);
        if (lane == 0) {
            #pragma unroll
            for (int k = 0; k < 7; k++) hp[m][k] = a[k];
        }
    }
    __syncthreads();

    // --- stage 3: final (G-mix of heads, normalize, quat, outputs) ---
    if (tid < NN) {
        const int m = tid;
        float l0 = locb[0], l1 = locb[1], l2 = locb[2];
        float z0 = logzb[0], z1 = logzb[1], z2 = logzb[2], z3 = logzb[3];
        #pragma unroll 4
        for (int n = 0; n < NN; n++) {
            float w = sG[m * NN + n];
            l0 += w * hp[n][0]; l1 += w * hp[n][1]; l2 += w * hp[n][2];
            z0 += w * hp[n][3]; z1 += w * hp[n][4];
            z2 += w * hp[n][5]; z3 += w * hp[n][6];
        }
        float r = rsqrtf(1.0f + l0 * l0 + l1 * l1 + l2 * l2);
        float d0 = r, d1 = l0 * r, d2 = l1 * r, d3 = l2 * r;
        float* ls = &g_ls[((long)b * NN + m) * 4];
        float w1 = ls[0], x1 = ls[1], y1 = ls[2], zz1 = ls[3];
        float q0 = w1 * d0 - x1 * d1 - y1 * d2 - zz1 * d3;
        float q1 = w1 * d1 + x1 * d0 + y1 * d3 - zz1 * d2;
        float q2 = w1 * d2 - x1 * d3 + y1 * d0 + zz1 * d1;
        float q3 = w1 * d3 + x1 * d2 - y1 * d1 + zz1 * d0;
        ls[0] = q0; ls[1] = q1; ls[2] = q2; ls[3] = q3;
        long ob = (((long)b * TT + t) * NN + m) * 4;
        out[ob + 0] = q0; out[ob + 1] = q1; out[ob + 2] = q2; out[ob + 3] = q3;
        const long ZOFF = (long)BB * TT * NN * 4;
        out[ZOFF + ob + 0] = z0; out[ZOFF + ob + 1] = z1;
        out[ZOFF + ob + 2] = z2; out[ZOFF + ob + 3] = z3;
        float* xr = &g_xi[((long)b * NN + m) * XIF];
        xr[64] = q0; xr[65] = q1; xr[66] = q2; xr[67] = q3;
        xr[68] = d0; xr[69] = d1; xr[70] = d2; xr[71] = d3;
    }
}

// ---------------- host ----------------
extern "C" void kernel_launch(void* const* d_in, const int* in_sizes, int n_in,
                              void* d_out, int out_size)
{
    const float* x     = (const float*)d_in[0];
    const float* enc   = (const float*)d_in[1];
    const float* z     = (const float*)d_in[2];
    /* d_in[3] = y, unused by the reference */
    const float* G     = (const float*)d_in[4];
    const float* Wx0   = (const float*)d_in[5];
    const float* Wh0   = (const float*)d_in[6];
    const float* b0    = (const float*)d_in[7];
    const float* Wx1   = (const float*)d_in[8];
    const float* Wh1   = (const float*)d_in[9];
    const float* b1    = (const float*)d_in[10];
    const float* fcW   = (const float*)d_in[11];
    const float* fcb   = (const float*)d_in[12];
    const float* fc2W  = (const float*)d_in[13];
    const float* fc2b  = (const float*)d_in[14];
    const float* ih1W  = (const float*)d_in[15];
    const float* ih1b  = (const float*)d_in[16];
    const float* ih2W  = (const float*)d_in[17];
    const float* ih2b  = (const float*)d_in[18];
    const float* locW  = (const float*)d_in[19];
    const float* locb  = (const float*)d_in[20];
    const float* logzW = (const float*)d_in[21];
    const float* logzb = (const float*)d_in[22];
    float* out = (float*)d_out;

    float *xi, *h1, *c1, *h2, *c2, *gts, *p1, *p2, *yi;
    cudaGetSymbolAddress((void**)&xi,  g_xi);
    cudaGetSymbolAddress((void**)&h1,  g_h1);
    cudaGetSymbolAddress((void**)&c1,  g_c1);
    cudaGetSymbolAddress((void**)&h2,  g_h2);
    cudaGetSymbolAddress((void**)&c2,  g_c2);
    cudaGetSymbolAddress((void**)&gts, g_gts);
    cudaGetSymbolAddress((void**)&p1,  g_p1);
    cudaGetSymbolAddress((void**)&p2,  g_p2);
    cudaGetSymbolAddress((void**)&yi,  g_yi);

    // ---- init ----
    {
        int tot = BB * NN * XIF;
        k_init_xi<<<(tot + 255) / 256, 256>>>(x, z);
    }
    // fused: enc @ ih1_W -> p1 (z=0) and enc @ ih2_W -> p2 (z=1)
    {
        dim3 grid(1, (BB * NN) / 128, 2);
        gemm_bf<<<grid, 256>>>(enc, 0, HH, HH,
                               enc, 0, HH, 0,
                               ih1W, ih2W, 0,
                               ih1W, 0,
                               ih1b, ih2b, 0,
                               p1, p2, 0, OUTF, OUTF, 1);
    }
    k_mix_init_f<<<BB, 256>>>(p1, p2, G);

    // ---- T sequential steps ----
    for (int t = 0; t < TT; t++) {
        // LSTM1 gates: xi @ Wx0[n] + h1 @ Wh0[n] + b0[n]
        {
            dim3 grid(G4 / 128, BB / 128, NN);
            gemm_bf<<<grid, 256>>>(xi, XIF, NN * XIF, XIF,
                                   h1, OUTF, NN * OUTF, OUTF,
                                   Wx0, Wx0, (long)XIF * G4,
                                   Wh0, (long)OUTF * G4,
                                   b0, b0, G4,
                                   gts, gts, G4, NN * G4, G4, NN);
        }
        { dim3 grid(2, BB); k_mix_lstm_f<<<grid, 256>>>(gts, G, h1, c1, nullptr); }
        // LSTM2 gates: h1 @ Wx1[n] + h2 @ Wh1[n] + b1[n]
        {
            dim3 grid(G4 / 128, BB / 128, NN);
            gemm_bf<<<grid, 256>>>(h1, OUTF, NN * OUTF, OUTF,
                                   h2, OUTF, NN * OUTF, OUTF,
                                   Wx1, Wx1, (long)OUTF * G4,
                                   Wh1, (long)OUTF * G4,
                                   b1, b1, G4,
                                   gts, gts, G4, NN * G4, G4, NN);
        }
        { dim3 grid(2, BB); k_mix_lstm_f<<<grid, 256>>>(gts, G, h2, c2, yi); }
        // fused fc / fc2: yi @ fc_W[n] -> p1 (z<24), yi @ fc2_W[n] -> p2 (z>=24)
        {
            dim3 grid(1, BB / 128, 2 * NN);
            gemm_bf<<<grid, 256>>>(yi, OUTF, NN * OUTF, OUTF,
                                   yi, OUTF, NN * OUTF, 0,
                                   fcW, fc2W, (long)OUTF * OUTF,
                                   fcW, 0,
                                   fcb, fc2b, OUTF,
                                   p1, p2, OUTF, NN * OUTF, OUTF, NN);
        }
        // fused tail: mix+tanh, head projections, final
        k_tail<<<BB, 256>>>(p1, p2, G, locW, locb, logzW, logzb, out, t);
    }
}